// round 14
// baseline (speedup 1.0000x reference)
#include <cuda_runtime.h>
#include <math.h>
#include <stdint.h>

#define NN 32768
#define KK 512
#define DD 64
#define SK_ITERS 100
#define NB 444
#define RPB ((NN + NB - 1) / NB)   // 74

__device__ __align__(16) float  g_E[(size_t)NN * KK];   // E (f32), 64 MiB
__device__ __align__(16) float  g_D[(size_t)NN * KK];   // d, then dc (f32)
__device__ float    g_rx[NN], g_rc[KK];
__device__ double   g_sum[3][KK];
__device__ double   g_lnv[KK];
__device__ unsigned g_dmax_u, g_dmin_u;
__device__ float    g_mid, g_amp;
__device__ double   g_loss;
__device__ unsigned g_arrive, g_release;

__global__ void k_init() {
    int t = threadIdx.x;
    if (t < KK) { g_sum[0][t] = 0.0; g_sum[1][t] = 0.0; g_sum[2][t] = 0.0; }
    if (t == 0) {
        g_dmax_u = 0u; g_dmin_u = 0x7f7fffffu; g_loss = 0.0;
        g_arrive = 0u; g_release = 0u;
    }
}

// XLA:GPU warp row-reduce (bitwise-frozen)
__global__ void k_rx(const float* __restrict__ x) {
    int warp = (blockIdx.x * blockDim.x + threadIdx.x) >> 5;
    int lane = threadIdx.x & 31;
    if (warp >= NN) return;
    const float* p = x + (size_t)warp * DD;
    float s = __fadd_rn(__fmul_rn(p[lane], p[lane]),
                        __fmul_rn(p[lane + 32], p[lane + 32]));
    #pragma unroll
    for (int o = 16; o; o >>= 1) s = __fadd_rn(s, __shfl_xor_sync(~0u, s, o));
    if (lane == 0) g_rx[warp] = s;
}
__global__ void k_rc(const float* __restrict__ cb) {
    int warp = (blockIdx.x * blockDim.x + threadIdx.x) >> 5;
    int lane = threadIdx.x & 31;
    if (warp >= KK) return;
    const float* p = cb + (size_t)warp * DD;
    float s = __fadd_rn(__fmul_rn(p[lane], p[lane]),
                        __fmul_rn(p[lane + 32], p[lane + 32]));
    #pragma unroll
    for (int o = 16; o; o >>= 1) s = __fadd_rn(s, __shfl_xor_sync(~0u, s, o));
    if (lane == 0) g_rc[warp] = s;
}

// d = fl(fl(rx+rc) - fl(2*mm)); mm = strict ascending-k single-FMA f32 chain (frozen)
__global__ __launch_bounds__(256) void k_gemm(const float* __restrict__ x,
                                              const float* __restrict__ cb) {
    __shared__ float xs[128][DD];
    __shared__ float cs[32][DD + 1];
    __shared__ float red[16];
    int b = blockIdx.x, row0 = b * 128, t = threadIdx.x;
    int jj = t & 31, rg = t >> 5;

    for (int i = t; i < 128 * DD; i += 256)
        xs[i / DD][i % DD] = x[(size_t)row0 * DD + i];

    float dmx = 0.0f, dmn = 3.4e38f;
    for (int ct = 0; ct < 16; ct++) {
        __syncthreads();
        for (int i = t; i < 32 * DD; i += 256)
            cs[i / DD][i % DD] = cb[(size_t)(ct * 32) * DD + i];
        __syncthreads();
        float cj[DD];
        #pragma unroll
        for (int k = 0; k < DD; k++) cj[k] = cs[jj][k];
        int jglob = ct * 32 + jj;
        float rcj = g_rc[jglob];

        for (int ii = 0; ii < 16; ii += 4) {
            int i0 = rg * 16 + ii;
            float a0 = 0.f, a1 = 0.f, a2 = 0.f, a3 = 0.f;
            #pragma unroll
            for (int k4 = 0; k4 < DD; k4 += 4) {
                float4 x0 = *(const float4*)&xs[i0 + 0][k4];
                float4 x1 = *(const float4*)&xs[i0 + 1][k4];
                float4 x2 = *(const float4*)&xs[i0 + 2][k4];
                float4 x3 = *(const float4*)&xs[i0 + 3][k4];
                a0 = __fmaf_rn(x0.x, cj[k4+0], a0); a0 = __fmaf_rn(x0.y, cj[k4+1], a0);
                a0 = __fmaf_rn(x0.z, cj[k4+2], a0); a0 = __fmaf_rn(x0.w, cj[k4+3], a0);
                a1 = __fmaf_rn(x1.x, cj[k4+0], a1); a1 = __fmaf_rn(x1.y, cj[k4+1], a1);
                a1 = __fmaf_rn(x1.z, cj[k4+2], a1); a1 = __fmaf_rn(x1.w, cj[k4+3], a1);
                a2 = __fmaf_rn(x2.x, cj[k4+0], a2); a2 = __fmaf_rn(x2.y, cj[k4+1], a2);
                a2 = __fmaf_rn(x2.z, cj[k4+2], a2); a2 = __fmaf_rn(x2.w, cj[k4+3], a2);
                a3 = __fmaf_rn(x3.x, cj[k4+0], a3); a3 = __fmaf_rn(x3.y, cj[k4+1], a3);
                a3 = __fmaf_rn(x3.z, cj[k4+2], a3); a3 = __fmaf_rn(x3.w, cj[k4+3], a3);
            }
            float mm[4] = {a0, a1, a2, a3};
            #pragma unroll
            for (int r = 0; r < 4; r++) {
                int i = i0 + r;
                float S = __fadd_rn(g_rx[row0 + i], rcj);
                float d = __fsub_rn(S, __fmul_rn(2.0f, mm[r]));
                dmx = fmaxf(dmx, d); dmn = fminf(dmn, d);
                g_D[(size_t)(row0 + i) * KK + jglob] = d;
            }
        }
    }
    #pragma unroll
    for (int o = 16; o; o >>= 1) {
        dmx = fmaxf(dmx, __shfl_xor_sync(~0u, dmx, o));
        dmn = fminf(dmn, __shfl_xor_sync(~0u, dmn, o));
    }
    int w = t >> 5;
    if ((t & 31) == 0) { red[w] = dmx; red[w + 8] = dmn; }
    __syncthreads();
    if (t == 0) {
        float m = red[0], n = red[8];
        for (int i = 1; i < 8; i++) { m = fmaxf(m, red[i]); n = fminf(n, red[i + 8]); }
        atomicMax(&g_dmax_u, __float_as_uint(m));
        atomicMin(&g_dmin_u, __float_as_uint(n));
    }
}

__global__ void k_scale() {
    float dmax = __uint_as_float(g_dmax_u), dmin = __uint_as_float(g_dmin_u);
    float mid = __fmul_rn(__fadd_rn(dmax, dmin), 0.5f);
    g_mid = mid;
    g_amp = __fadd_rn(__fsub_rn(dmax, mid), 1e-5f);
}

// dc = fl((d-mid)/amp) bitwise -> g_D;  E = expf((rmin-dc)/eps) -> g_E
__global__ __launch_bounds__(256) void k_rowE() {
    int warp = (blockIdx.x * blockDim.x + threadIdx.x) >> 5;
    int lane = threadIdx.x & 31;
    if (warp >= NN) return;
    float mid = g_mid, amp = g_amp;
    float4* Dr = (float4*)&g_D[(size_t)warp * KK];
    float4* Er = (float4*)&g_E[(size_t)warp * KK];

    float4 dcv[4];
    float rmin = 3.4e38f;
    #pragma unroll
    for (int k = 0; k < 4; k++) {
        float4 d = Dr[lane + 32 * k];
        d.x = __fdiv_rn(__fsub_rn(d.x, mid), amp);
        d.y = __fdiv_rn(__fsub_rn(d.y, mid), amp);
        d.z = __fdiv_rn(__fsub_rn(d.z, mid), amp);
        d.w = __fdiv_rn(__fsub_rn(d.w, mid), amp);
        rmin = fminf(rmin, fminf(fminf(d.x, d.y), fminf(d.z, d.w)));
        dcv[k] = d;
    }
    #pragma unroll
    for (int o = 16; o; o >>= 1) rmin = fminf(rmin, __shfl_xor_sync(~0u, rmin, o));

    const float INV_EPS = 333.33333333333333f;
    #pragma unroll
    for (int k = 0; k < 4; k++) {
        float4 d = dcv[k], e;
        Dr[lane + 32 * k] = d;
        e.x = expf(__fmul_rn(__fsub_rn(rmin, d.x), INV_EPS));
        e.y = expf(__fmul_rn(__fsub_rn(rmin, d.y), INV_EPS));
        e.z = expf(__fmul_rn(__fsub_rn(rmin, d.z), INV_EPS));
        e.w = expf(__fmul_rn(__fsub_rn(rmin, d.w), INV_EPS));
        Er[lane + 32 * k] = e;
    }
}

// fast reciprocal (u precision is argmax-cancelling; 2^-23 rel err,
// within the R7-vs-R12-validated trajectory noise envelope)
__device__ __forceinline__ float frcp(float a) {
    float r;
    asm("rcp.approx.f32 %0, %1;" : "=f"(r) : "f"(a));
    return r;
}

// sense-forward grid barrier (all NB blocks resident by construction)
__device__ __forceinline__ void gridbar(unsigned gen) {
    __syncthreads();
    if (threadIdx.x == 0) {
        __threadfence();
        unsigned t = atomicAdd(&g_arrive, 1u);
        if (t == NB - 1) {
            g_arrive = 0u;
            __threadfence();
            atomicExch(&g_release, gen);
        } else {
            while (atomicAdd(&g_release, 0u) < gen) __nanosleep(128);
        }
    }
    __syncthreads();
}

// ALL Sinkhorn iterations in one persistent kernel; 3 blocks/SM.
__global__ __launch_bounds__(256, 3) void k_sinkp() {
    __shared__ float sv[KK];
    __shared__ float shS[8][KK];   // 16 KB
    int b = blockIdx.x, t = threadIdx.x, w = t >> 5, lane = t & 31;
    int row0 = b * RPB, row1 = min(row0 + RPB, NN);
    if (row0 > NN) row0 = NN;

    for (int it = 0; it < SK_ITERS; it++) {
        int prev = (it + 2) % 3, cur = it % 3, nxt = (it + 1) % 3;
        if (it == 0) {
            for (int j = t; j < KK; j += 256) sv[j] = 1.0f;
        } else {
            for (int j = t; j < KK; j += 256)
                sv[j] = (float)(1.0 / (512.0 * g_sum[prev][j]));
        }
        for (int j = t; j < KK; j += 256) g_sum[nxt][j] = 0.0;
        __syncthreads();

        float4 vr[4];
        #pragma unroll
        for (int k = 0; k < 4; k++) vr[k] = *(const float4*)&sv[4 * lane + 128 * k];
        float4 cpA[4], cpB[4];
        #pragma unroll
        for (int k = 0; k < 4; k++) {
            cpA[k] = make_float4(0.f, 0.f, 0.f, 0.f);
            cpB[k] = make_float4(0.f, 0.f, 0.f, 0.f);
        }

        int par = 0;
        for (int r = row0 + w; r < row1; r += 8, par ^= 1) {
            const float4* Er = (const float4*)&g_E[(size_t)r * KK];
            float4 e[4];
            #pragma unroll
            for (int k = 0; k < 4; k++) e[k] = Er[lane + 32 * k];
            float d0 = 0.f, d1 = 0.f, d2 = 0.f, d3 = 0.f;
            #pragma unroll
            for (int k = 0; k < 4; k++) {
                d0 = fmaf(e[k].x, vr[k].x, d0);
                d1 = fmaf(e[k].y, vr[k].y, d1);
                d2 = fmaf(e[k].z, vr[k].z, d2);
                d3 = fmaf(e[k].w, vr[k].w, d3);
            }
            float dot = (d0 + d1) + (d2 + d3);
            #pragma unroll
            for (int o = 16; o; o >>= 1) dot += __shfl_xor_sync(~0u, dot, o);
            float u = frcp(32768.0f * dot);
            float4* cp = par ? cpB : cpA;
            #pragma unroll
            for (int k = 0; k < 4; k++) {
                cp[k].x = fmaf(e[k].x, u, cp[k].x);
                cp[k].y = fmaf(e[k].y, u, cp[k].y);
                cp[k].z = fmaf(e[k].z, u, cp[k].z);
                cp[k].w = fmaf(e[k].w, u, cp[k].w);
            }
        }
        #pragma unroll
        for (int k = 0; k < 4; k++) {
            float4 s;
            s.x = cpA[k].x + cpB[k].x; s.y = cpA[k].y + cpB[k].y;
            s.z = cpA[k].z + cpB[k].z; s.w = cpA[k].w + cpB[k].w;
            *(float4*)&shS[w][4 * lane + 128 * k] = s;
        }
        __syncthreads();
        for (int j = t; j < KK; j += 256) {
            double a = 0.0;
            #pragma unroll
            for (int wi = 0; wi < 8; wi++) a += (double)shS[wi][j];
            atomicAdd(&g_sum[cur][j], a);
        }
        gridbar(it + 1);
    }
}

__global__ void k_lnv(int last) {
    int j = threadIdx.x;  // 512
    double s = g_sum[last][j];
    if (s < 1e-300) s = 1e-300;
    g_lnv[j] = log(1.0 / (512.0 * s));
}

// final: f64 scores s_j = ln v_j - dc_ij/0.003 on frozen dc
__global__ void k_out(const float* __restrict__ x, const float* __restrict__ cb,
                      float* __restrict__ oxq, float* __restrict__ oidx) {
    int warp = (blockIdx.x * blockDim.x + threadIdx.x) >> 5;
    int lane = threadIdx.x & 31;
    if (warp >= NN) return;
    int r = warp;

    const float4* Dr = (const float4*)&g_D[(size_t)r * KK];
    double best = -1e300;
    int bidx = 0;
    #pragma unroll
    for (int k = 0; k < 4; k++) {
        float4 d = Dr[lane + 32 * k];
        int c0 = 4 * lane + 128 * k;
        float dv[4] = {d.x, d.y, d.z, d.w};
        #pragma unroll
        for (int c = 0; c < 4; c++) {
            double s = g_lnv[c0 + c] - (double)dv[c] / 0.003;
            if (s > best) { best = s; bidx = c0 + c; }
        }
    }
    #pragma unroll
    for (int o = 16; o; o >>= 1) {
        double ov = __shfl_xor_sync(~0u, best, o);
        int oi = __shfl_xor_sync(~0u, bidx, o);
        if (ov > best || (ov == best && oi < bidx)) { best = ov; bidx = oi; }
    }

    const float* c = cb + (size_t)bidx * DD;
    const float* xr = x + (size_t)r * DD;
    float a0 = c[lane], a1 = c[lane + 32];
    float x0 = xr[lane], x1 = xr[lane + 32];
    if (oxq) {
        oxq[(size_t)r * DD + lane]      = __fadd_rn(x0, __fsub_rn(a0, x0));
        oxq[(size_t)r * DD + lane + 32] = __fadd_rn(x1, __fsub_rn(a1, x1));
    }
    float d0 = __fsub_rn(a0, x0), d1 = __fsub_rn(a1, x1);
    double ls = (double)__fmul_rn(d0, d0) + (double)__fmul_rn(d1, d1);
    #pragma unroll
    for (int o = 16; o; o >>= 1) ls += __shfl_xor_sync(~0u, ls, o);
    if (lane == 0) {
        if (oidx) oidx[r] = (float)bidx;
        atomicAdd(&g_loss, ls);
    }
}

__global__ void k_loss(float* __restrict__ ol) {
    if (ol) {
        float c = (float)(g_loss / (double)((size_t)NN * DD));
        ol[0] = __fadd_rn(c, __fmul_rn(0.25f, c));
    }
}

extern "C" void kernel_launch(void* const* d_in, const int* in_sizes, int n_in,
                              void* d_out, int out_size) {
    const float* x = (const float*)d_in[0];
    const float* cb = (const float*)d_in[1];
    if (n_in >= 2 && in_sizes[0] == KK * DD && in_sizes[1] == NN * DD) {
        const float* tmp = x; x = cb; cb = tmp;
    }
    float* out = (float*)d_out;
    float* oxq = (out_size >= NN * DD) ? out : nullptr;
    float* ols = (out_size >= NN * DD + 1) ? out + (size_t)NN * DD : nullptr;
    float* oidx = (out_size >= NN * DD + 1 + NN) ? out + (size_t)NN * DD + 1 : nullptr;

    k_init<<<1, 512>>>();
    k_rx<<<NN / 8, 256>>>(x);
    k_rc<<<KK / 8, 256>>>(cb);
    k_gemm<<<NN / 128, 256>>>(x, cb);
    k_scale<<<1, 1>>>();
    k_rowE<<<NN / 8, 256>>>();
    k_sinkp<<<NB, 256>>>();
    k_lnv<<<1, KK>>>((SK_ITERS - 1) % 3);
    k_out<<<NN / 8, 256>>>(x, cb, oxq, oidx);
    k_loss<<<1, 1>>>(ols);
}

// round 15
// speedup vs baseline: 1.2190x; 1.2190x over previous
#include <cuda_runtime.h>
#include <math.h>
#include <stdint.h>

#define NN 32768
#define KK 512
#define DD 64
#define SK_ITERS 100
#define NB 296
#define RPB ((NN + NB - 1) / NB)   // 111

__device__ __align__(16) float  g_E[(size_t)NN * KK];   // E (f32), 64 MiB
__device__ __align__(16) float  g_D[(size_t)NN * KK];   // d, then dc (f32)
__device__ float    g_rx[NN], g_rc[KK];
__device__ double   g_sum[3][KK];
__device__ double   g_lnv[KK];
__device__ unsigned g_dmax_u, g_dmin_u;
__device__ float    g_mid, g_amp;
__device__ double   g_loss;

__global__ void k_init() {
    int t = threadIdx.x;
    if (t < KK) { g_sum[0][t] = 0.0; g_sum[1][t] = 0.0; g_sum[2][t] = 0.0; }
    if (t == 0) { g_dmax_u = 0u; g_dmin_u = 0x7f7fffffu; g_loss = 0.0; }
}

// XLA:GPU warp row-reduce (bitwise-frozen)
__global__ void k_rx(const float* __restrict__ x) {
    int warp = (blockIdx.x * blockDim.x + threadIdx.x) >> 5;
    int lane = threadIdx.x & 31;
    if (warp >= NN) return;
    const float* p = x + (size_t)warp * DD;
    float s = __fadd_rn(__fmul_rn(p[lane], p[lane]),
                        __fmul_rn(p[lane + 32], p[lane + 32]));
    #pragma unroll
    for (int o = 16; o; o >>= 1) s = __fadd_rn(s, __shfl_xor_sync(~0u, s, o));
    if (lane == 0) g_rx[warp] = s;
}
__global__ void k_rc(const float* __restrict__ cb) {
    int warp = (blockIdx.x * blockDim.x + threadIdx.x) >> 5;
    int lane = threadIdx.x & 31;
    if (warp >= KK) return;
    const float* p = cb + (size_t)warp * DD;
    float s = __fadd_rn(__fmul_rn(p[lane], p[lane]),
                        __fmul_rn(p[lane + 32], p[lane + 32]));
    #pragma unroll
    for (int o = 16; o; o >>= 1) s = __fadd_rn(s, __shfl_xor_sync(~0u, s, o));
    if (lane == 0) g_rc[warp] = s;
}

// d = fl(fl(rx+rc) - fl(2*mm)); mm = strict ascending-k single-FMA f32 chain (frozen)
__global__ __launch_bounds__(256, 3) void k_gemm(const float* __restrict__ x,
                                                 const float* __restrict__ cb) {
    __shared__ float xs[128][DD];
    __shared__ float cs[32][DD + 1];
    __shared__ float red[16];
    int b = blockIdx.x, row0 = b * 128, t = threadIdx.x;
    int jj = t & 31, rg = t >> 5;

    for (int i = t; i < 128 * DD; i += 256)
        xs[i / DD][i % DD] = x[(size_t)row0 * DD + i];

    float dmx = 0.0f, dmn = 3.4e38f;
    for (int ct = 0; ct < 16; ct++) {
        __syncthreads();
        for (int i = t; i < 32 * DD; i += 256)
            cs[i / DD][i % DD] = cb[(size_t)(ct * 32) * DD + i];
        __syncthreads();
        float cj[DD];
        #pragma unroll
        for (int k = 0; k < DD; k++) cj[k] = cs[jj][k];
        int jglob = ct * 32 + jj;
        float rcj = g_rc[jglob];

        for (int ii = 0; ii < 16; ii += 2) {
            int i0 = rg * 16 + ii;
            float a0 = 0.f, a1 = 0.f;
            #pragma unroll
            for (int k4 = 0; k4 < DD; k4 += 4) {
                float4 x0 = *(const float4*)&xs[i0 + 0][k4];
                float4 x1 = *(const float4*)&xs[i0 + 1][k4];
                a0 = __fmaf_rn(x0.x, cj[k4+0], a0); a0 = __fmaf_rn(x0.y, cj[k4+1], a0);
                a0 = __fmaf_rn(x0.z, cj[k4+2], a0); a0 = __fmaf_rn(x0.w, cj[k4+3], a0);
                a1 = __fmaf_rn(x1.x, cj[k4+0], a1); a1 = __fmaf_rn(x1.y, cj[k4+1], a1);
                a1 = __fmaf_rn(x1.z, cj[k4+2], a1); a1 = __fmaf_rn(x1.w, cj[k4+3], a1);
            }
            float mm[2] = {a0, a1};
            #pragma unroll
            for (int r = 0; r < 2; r++) {
                int i = i0 + r;
                float S = __fadd_rn(g_rx[row0 + i], rcj);
                float d = __fsub_rn(S, __fmul_rn(2.0f, mm[r]));
                dmx = fmaxf(dmx, d); dmn = fminf(dmn, d);
                g_D[(size_t)(row0 + i) * KK + jglob] = d;
            }
        }
    }
    #pragma unroll
    for (int o = 16; o; o >>= 1) {
        dmx = fmaxf(dmx, __shfl_xor_sync(~0u, dmx, o));
        dmn = fminf(dmn, __shfl_xor_sync(~0u, dmn, o));
    }
    int w = t >> 5;
    if ((t & 31) == 0) { red[w] = dmx; red[w + 8] = dmn; }
    __syncthreads();
    if (t == 0) {
        float m = red[0], n = red[8];
        for (int i = 1; i < 8; i++) { m = fmaxf(m, red[i]); n = fminf(n, red[i + 8]); }
        atomicMax(&g_dmax_u, __float_as_uint(m));
        atomicMin(&g_dmin_u, __float_as_uint(n));
    }
}

__global__ void k_scale() {
    float dmax = __uint_as_float(g_dmax_u), dmin = __uint_as_float(g_dmin_u);
    float mid = __fmul_rn(__fadd_rn(dmax, dmin), 0.5f);
    g_mid = mid;
    g_amp = __fadd_rn(__fsub_rn(dmax, mid), 1e-5f);
}

// dc = fl((d-mid)/amp) bitwise -> g_D;  E = expf((rmin-dc)/eps) -> g_E
__global__ __launch_bounds__(256) void k_rowE() {
    int warp = (blockIdx.x * blockDim.x + threadIdx.x) >> 5;
    int lane = threadIdx.x & 31;
    if (warp >= NN) return;
    float mid = g_mid, amp = g_amp;
    float4* Dr = (float4*)&g_D[(size_t)warp * KK];
    float4* Er = (float4*)&g_E[(size_t)warp * KK];

    float4 dcv[4];
    float rmin = 3.4e38f;
    #pragma unroll
    for (int k = 0; k < 4; k++) {
        float4 d = Dr[lane + 32 * k];
        d.x = __fdiv_rn(__fsub_rn(d.x, mid), amp);
        d.y = __fdiv_rn(__fsub_rn(d.y, mid), amp);
        d.z = __fdiv_rn(__fsub_rn(d.z, mid), amp);
        d.w = __fdiv_rn(__fsub_rn(d.w, mid), amp);
        rmin = fminf(rmin, fminf(fminf(d.x, d.y), fminf(d.z, d.w)));
        dcv[k] = d;
    }
    #pragma unroll
    for (int o = 16; o; o >>= 1) rmin = fminf(rmin, __shfl_xor_sync(~0u, rmin, o));

    const float INV_EPS = 333.33333333333333f;
    #pragma unroll
    for (int k = 0; k < 4; k++) {
        float4 d = dcv[k], e;
        Dr[lane + 32 * k] = d;
        e.x = expf(__fmul_rn(__fsub_rn(rmin, d.x), INV_EPS));
        e.y = expf(__fmul_rn(__fsub_rn(rmin, d.y), INV_EPS));
        e.z = expf(__fmul_rn(__fsub_rn(rmin, d.z), INV_EPS));
        e.w = expf(__fmul_rn(__fsub_rn(rmin, d.w), INV_EPS));
        Er[lane + 32 * k] = e;
    }
}

// one Sinkhorn iteration: two rows per warp step, chains interleaved (ILP).
// Per-row arithmetic & parity accumulators bit-identical to the R12 champion.
__global__ __launch_bounds__(256, 2) void k_sink(int it) {
    __shared__ float sv[KK];
    __shared__ float shS[8][KK];   // 16 KB
    int b = blockIdx.x, t = threadIdx.x, w = t >> 5, lane = t & 31;
    int row0 = b * RPB, row1 = min(row0 + RPB, NN);
    int prev = (it + 2) % 3, cur = it % 3, nxt = (it + 1) % 3;

    if (it == 0) {
        for (int j = t; j < KK; j += 256) sv[j] = 1.0f;
    } else {
        for (int j = t; j < KK; j += 256)
            sv[j] = (float)(1.0 / (512.0 * g_sum[prev][j]));
    }
    for (int j = t; j < KK; j += 256) g_sum[nxt][j] = 0.0;
    __syncthreads();

    float4 vr[4];
    #pragma unroll
    for (int k = 0; k < 4; k++) vr[k] = *(const float4*)&sv[4 * lane + 128 * k];
    float4 cpA[4], cpB[4];
    #pragma unroll
    for (int k = 0; k < 4; k++) {
        cpA[k] = make_float4(0.f, 0.f, 0.f, 0.f);
        cpB[k] = make_float4(0.f, 0.f, 0.f, 0.f);
    }

    for (int r = row0 + w; r < row1; r += 16) {
        int r1 = r + 8;
        bool two = (r1 < row1);
        const float4* Er0 = (const float4*)&g_E[(size_t)r * KK];
        const float4* Er1 = (const float4*)&g_E[(size_t)(two ? r1 : r) * KK];
        float4 e0[4], e1[4];
        #pragma unroll
        for (int k = 0; k < 4; k++) { e0[k] = Er0[lane + 32 * k]; e1[k] = Er1[lane + 32 * k]; }

        float p0 = 0.f, p1 = 0.f, p2 = 0.f, p3 = 0.f;
        float q0 = 0.f, q1 = 0.f, q2 = 0.f, q3 = 0.f;
        #pragma unroll
        for (int k = 0; k < 4; k++) {
            p0 = fmaf(e0[k].x, vr[k].x, p0); q0 = fmaf(e1[k].x, vr[k].x, q0);
            p1 = fmaf(e0[k].y, vr[k].y, p1); q1 = fmaf(e1[k].y, vr[k].y, q1);
            p2 = fmaf(e0[k].z, vr[k].z, p2); q2 = fmaf(e1[k].z, vr[k].z, q2);
            p3 = fmaf(e0[k].w, vr[k].w, p3); q3 = fmaf(e1[k].w, vr[k].w, q3);
        }
        float dot0 = (p0 + p1) + (p2 + p3);
        float dot1 = (q0 + q1) + (q2 + q3);
        #pragma unroll
        for (int o = 16; o; o >>= 1) {
            dot0 += __shfl_xor_sync(~0u, dot0, o);
            dot1 += __shfl_xor_sync(~0u, dot1, o);
        }
        float u0 = __fdiv_rn(1.0f, 32768.0f * dot0);
        float u1 = __fdiv_rn(1.0f, 32768.0f * dot1);
        #pragma unroll
        for (int k = 0; k < 4; k++) {
            cpA[k].x = fmaf(e0[k].x, u0, cpA[k].x);
            cpA[k].y = fmaf(e0[k].y, u0, cpA[k].y);
            cpA[k].z = fmaf(e0[k].z, u0, cpA[k].z);
            cpA[k].w = fmaf(e0[k].w, u0, cpA[k].w);
        }
        if (two) {
            #pragma unroll
            for (int k = 0; k < 4; k++) {
                cpB[k].x = fmaf(e1[k].x, u1, cpB[k].x);
                cpB[k].y = fmaf(e1[k].y, u1, cpB[k].y);
                cpB[k].z = fmaf(e1[k].z, u1, cpB[k].z);
                cpB[k].w = fmaf(e1[k].w, u1, cpB[k].w);
            }
        }
    }
    #pragma unroll
    for (int k = 0; k < 4; k++) {
        float4 s;
        s.x = cpA[k].x + cpB[k].x; s.y = cpA[k].y + cpB[k].y;
        s.z = cpA[k].z + cpB[k].z; s.w = cpA[k].w + cpB[k].w;
        *(float4*)&shS[w][4 * lane + 128 * k] = s;
    }
    __syncthreads();
    for (int j = t; j < KK; j += 256) {
        double a = 0.0;
        #pragma unroll
        for (int wi = 0; wi < 8; wi++) a += (double)shS[wi][j];
        atomicAdd(&g_sum[cur][j], a);
    }
}

__global__ void k_lnv(int last) {
    int j = threadIdx.x;  // 512
    double s = g_sum[last][j];
    if (s < 1e-300) s = 1e-300;
    g_lnv[j] = log(1.0 / (512.0 * s));
}

// final: f64 scores s_j = ln v_j - dc_ij/0.003 on frozen dc
__global__ void k_out(const float* __restrict__ x, const float* __restrict__ cb,
                      float* __restrict__ oxq, float* __restrict__ oidx) {
    int warp = (blockIdx.x * blockDim.x + threadIdx.x) >> 5;
    int lane = threadIdx.x & 31;
    if (warp >= NN) return;
    int r = warp;

    const float4* Dr = (const float4*)&g_D[(size_t)r * KK];
    double best = -1e300;
    int bidx = 0;
    #pragma unroll
    for (int k = 0; k < 4; k++) {
        float4 d = Dr[lane + 32 * k];
        int c0 = 4 * lane + 128 * k;
        float dv[4] = {d.x, d.y, d.z, d.w};
        #pragma unroll
        for (int c = 0; c < 4; c++) {
            double s = g_lnv[c0 + c] - (double)dv[c] / 0.003;
            if (s > best) { best = s; bidx = c0 + c; }
        }
    }
    #pragma unroll
    for (int o = 16; o; o >>= 1) {
        double ov = __shfl_xor_sync(~0u, best, o);
        int oi = __shfl_xor_sync(~0u, bidx, o);
        if (ov > best || (ov == best && oi < bidx)) { best = ov; bidx = oi; }
    }

    const float* c = cb + (size_t)bidx * DD;
    const float* xr = x + (size_t)r * DD;
    float a0 = c[lane], a1 = c[lane + 32];
    float x0 = xr[lane], x1 = xr[lane + 32];
    if (oxq) {
        oxq[(size_t)r * DD + lane]      = __fadd_rn(x0, __fsub_rn(a0, x0));
        oxq[(size_t)r * DD + lane + 32] = __fadd_rn(x1, __fsub_rn(a1, x1));
    }
    float d0 = __fsub_rn(a0, x0), d1 = __fsub_rn(a1, x1);
    double ls = (double)__fmul_rn(d0, d0) + (double)__fmul_rn(d1, d1);
    #pragma unroll
    for (int o = 16; o; o >>= 1) ls += __shfl_xor_sync(~0u, ls, o);
    if (lane == 0) {
        if (oidx) oidx[r] = (float)bidx;
        atomicAdd(&g_loss, ls);
    }
}

__global__ void k_loss(float* __restrict__ ol) {
    if (ol) {
        float c = (float)(g_loss / (double)((size_t)NN * DD));
        ol[0] = __fadd_rn(c, __fmul_rn(0.25f, c));
    }
}

extern "C" void kernel_launch(void* const* d_in, const int* in_sizes, int n_in,
                              void* d_out, int out_size) {
    const float* x = (const float*)d_in[0];
    const float* cb = (const float*)d_in[1];
    if (n_in >= 2 && in_sizes[0] == KK * DD && in_sizes[1] == NN * DD) {
        const float* tmp = x; x = cb; cb = tmp;
    }
    float* out = (float*)d_out;
    float* oxq = (out_size >= NN * DD) ? out : nullptr;
    float* ols = (out_size >= NN * DD + 1) ? out + (size_t)NN * DD : nullptr;
    float* oidx = (out_size >= NN * DD + 1 + NN) ? out + (size_t)NN * DD + 1 : nullptr;

    k_init<<<1, 512>>>();
    k_rx<<<NN / 8, 256>>>(x);
    k_rc<<<KK / 8, 256>>>(cb);
    k_gemm<<<NN / 128, 256>>>(x, cb);
    k_scale<<<1, 1>>>();
    k_rowE<<<NN / 8, 256>>>();
    for (int it = 0; it < SK_ITERS; it++)
        k_sink<<<NB, 256>>>(it);
    k_lnv<<<1, KK>>>((SK_ITERS - 1) % 3);
    k_out<<<NN / 8, 256>>>(x, cb, oxq, oidx);
    k_loss<<<1, 1>>>(ols);
}

// round 16
// speedup vs baseline: 1.2482x; 1.0240x over previous
#include <cuda_runtime.h>
#include <math.h>
#include <stdint.h>

#define NN 32768
#define KK 512
#define DD 64
#define SK_ITERS 100
#define NB 296
#define RPB ((NN + NB - 1) / NB)   // 111

__device__ __align__(16) float  g_E[(size_t)NN * KK];   // E (f32), 64 MiB
__device__ __align__(16) float  g_D[(size_t)NN * KK];   // d, then dc (f32)
__device__ float    g_rx[NN], g_rc[KK];
__device__ double   g_sum[3][KK];
__device__ double   g_lnv[KK];
__device__ unsigned g_dmax_u, g_dmin_u;
__device__ float    g_mid, g_amp;
__device__ double   g_loss;

__global__ void k_init() {
    int t = threadIdx.x;
    if (t < KK) { g_sum[0][t] = 0.0; g_sum[1][t] = 0.0; g_sum[2][t] = 0.0; }
    if (t == 0) { g_dmax_u = 0u; g_dmin_u = 0x7f7fffffu; g_loss = 0.0; }
}

// XLA:GPU warp row-reduce (bitwise-frozen)
__global__ void k_rx(const float* __restrict__ x) {
    int warp = (blockIdx.x * blockDim.x + threadIdx.x) >> 5;
    int lane = threadIdx.x & 31;
    if (warp >= NN) return;
    const float* p = x + (size_t)warp * DD;
    float s = __fadd_rn(__fmul_rn(p[lane], p[lane]),
                        __fmul_rn(p[lane + 32], p[lane + 32]));
    #pragma unroll
    for (int o = 16; o; o >>= 1) s = __fadd_rn(s, __shfl_xor_sync(~0u, s, o));
    if (lane == 0) g_rx[warp] = s;
}
__global__ void k_rc(const float* __restrict__ cb) {
    int warp = (blockIdx.x * blockDim.x + threadIdx.x) >> 5;
    int lane = threadIdx.x & 31;
    if (warp >= KK) return;
    const float* p = cb + (size_t)warp * DD;
    float s = __fadd_rn(__fmul_rn(p[lane], p[lane]),
                        __fmul_rn(p[lane + 32], p[lane + 32]));
    #pragma unroll
    for (int o = 16; o; o >>= 1) s = __fadd_rn(s, __shfl_xor_sync(~0u, s, o));
    if (lane == 0) g_rc[warp] = s;
}

// d = fl(fl(rx+rc) - fl(2*mm)); mm = strict ascending-k single-FMA f32 chain
// (R12-measured 103us version, verbatim)
__global__ __launch_bounds__(256) void k_gemm(const float* __restrict__ x,
                                              const float* __restrict__ cb) {
    __shared__ float xs[128][DD];
    __shared__ float cs[32][DD + 1];
    __shared__ float red[16];
    int b = blockIdx.x, row0 = b * 128, t = threadIdx.x;
    int jj = t & 31, rg = t >> 5;

    for (int i = t; i < 128 * DD; i += 256)
        xs[i / DD][i % DD] = x[(size_t)row0 * DD + i];

    float dmx = 0.0f, dmn = 3.4e38f;
    for (int ct = 0; ct < 16; ct++) {
        __syncthreads();
        for (int i = t; i < 32 * DD; i += 256)
            cs[i / DD][i % DD] = cb[(size_t)(ct * 32) * DD + i];
        __syncthreads();
        float cj[DD];
        #pragma unroll
        for (int k = 0; k < DD; k++) cj[k] = cs[jj][k];
        int jglob = ct * 32 + jj;
        float rcj = g_rc[jglob];

        for (int ii = 0; ii < 16; ii += 4) {
            int i0 = rg * 16 + ii;
            float a0 = 0.f, a1 = 0.f, a2 = 0.f, a3 = 0.f;
            #pragma unroll
            for (int k4 = 0; k4 < DD; k4 += 4) {
                float4 x0 = *(const float4*)&xs[i0 + 0][k4];
                float4 x1 = *(const float4*)&xs[i0 + 1][k4];
                float4 x2 = *(const float4*)&xs[i0 + 2][k4];
                float4 x3 = *(const float4*)&xs[i0 + 3][k4];
                a0 = __fmaf_rn(x0.x, cj[k4+0], a0); a0 = __fmaf_rn(x0.y, cj[k4+1], a0);
                a0 = __fmaf_rn(x0.z, cj[k4+2], a0); a0 = __fmaf_rn(x0.w, cj[k4+3], a0);
                a1 = __fmaf_rn(x1.x, cj[k4+0], a1); a1 = __fmaf_rn(x1.y, cj[k4+1], a1);
                a1 = __fmaf_rn(x1.z, cj[k4+2], a1); a1 = __fmaf_rn(x1.w, cj[k4+3], a1);
                a2 = __fmaf_rn(x2.x, cj[k4+0], a2); a2 = __fmaf_rn(x2.y, cj[k4+1], a2);
                a2 = __fmaf_rn(x2.z, cj[k4+2], a2); a2 = __fmaf_rn(x2.w, cj[k4+3], a2);
                a3 = __fmaf_rn(x3.x, cj[k4+0], a3); a3 = __fmaf_rn(x3.y, cj[k4+1], a3);
                a3 = __fmaf_rn(x3.z, cj[k4+2], a3); a3 = __fmaf_rn(x3.w, cj[k4+3], a3);
            }
            float mm[4] = {a0, a1, a2, a3};
            #pragma unroll
            for (int r = 0; r < 4; r++) {
                int i = i0 + r;
                float S = __fadd_rn(g_rx[row0 + i], rcj);
                float d = __fsub_rn(S, __fmul_rn(2.0f, mm[r]));
                dmx = fmaxf(dmx, d); dmn = fminf(dmn, d);
                g_D[(size_t)(row0 + i) * KK + jglob] = d;
            }
        }
    }
    #pragma unroll
    for (int o = 16; o; o >>= 1) {
        dmx = fmaxf(dmx, __shfl_xor_sync(~0u, dmx, o));
        dmn = fminf(dmn, __shfl_xor_sync(~0u, dmn, o));
    }
    int w = t >> 5;
    if ((t & 31) == 0) { red[w] = dmx; red[w + 8] = dmn; }
    __syncthreads();
    if (t == 0) {
        float m = red[0], n = red[8];
        for (int i = 1; i < 8; i++) { m = fmaxf(m, red[i]); n = fminf(n, red[i + 8]); }
        atomicMax(&g_dmax_u, __float_as_uint(m));
        atomicMin(&g_dmin_u, __float_as_uint(n));
    }
}

__global__ void k_scale() {
    float dmax = __uint_as_float(g_dmax_u), dmin = __uint_as_float(g_dmin_u);
    float mid = __fmul_rn(__fadd_rn(dmax, dmin), 0.5f);
    g_mid = mid;
    g_amp = __fadd_rn(__fsub_rn(dmax, mid), 1e-5f);
}

// dc = fl((d-mid)/amp) bitwise -> g_D;  E = expf((rmin-dc)/eps) -> g_E
__global__ __launch_bounds__(256) void k_rowE() {
    int warp = (blockIdx.x * blockDim.x + threadIdx.x) >> 5;
    int lane = threadIdx.x & 31;
    if (warp >= NN) return;
    float mid = g_mid, amp = g_amp;
    float4* Dr = (float4*)&g_D[(size_t)warp * KK];
    float4* Er = (float4*)&g_E[(size_t)warp * KK];

    float4 dcv[4];
    float rmin = 3.4e38f;
    #pragma unroll
    for (int k = 0; k < 4; k++) {
        float4 d = Dr[lane + 32 * k];
        d.x = __fdiv_rn(__fsub_rn(d.x, mid), amp);
        d.y = __fdiv_rn(__fsub_rn(d.y, mid), amp);
        d.z = __fdiv_rn(__fsub_rn(d.z, mid), amp);
        d.w = __fdiv_rn(__fsub_rn(d.w, mid), amp);
        rmin = fminf(rmin, fminf(fminf(d.x, d.y), fminf(d.z, d.w)));
        dcv[k] = d;
    }
    #pragma unroll
    for (int o = 16; o; o >>= 1) rmin = fminf(rmin, __shfl_xor_sync(~0u, rmin, o));

    const float INV_EPS = 333.33333333333333f;
    #pragma unroll
    for (int k = 0; k < 4; k++) {
        float4 d = dcv[k], e;
        Dr[lane + 32 * k] = d;
        e.x = expf(__fmul_rn(__fsub_rn(rmin, d.x), INV_EPS));
        e.y = expf(__fmul_rn(__fsub_rn(rmin, d.y), INV_EPS));
        e.z = expf(__fmul_rn(__fsub_rn(rmin, d.z), INV_EPS));
        e.w = expf(__fmul_rn(__fsub_rn(rmin, d.w), INV_EPS));
        Er[lane + 32 * k] = e;
    }
}

__device__ __forceinline__ float frcp(float a) {
    float r;
    asm("rcp.approx.f32 %0, %1;" : "=f"(r) : "f"(a));
    return r;
}

// one Sinkhorn iteration: FOUR rows per warp step, chains interleaved;
// rcp.approx for u (R14-validated); single accumulator set (order freedom validated).
__global__ __launch_bounds__(256, 2) void k_sink(int it) {
    __shared__ float sv[KK];
    __shared__ float shS[8][KK];   // 16 KB
    int b = blockIdx.x, t = threadIdx.x, w = t >> 5, lane = t & 31;
    int row0 = b * RPB, row1 = min(row0 + RPB, NN);
    int prev = (it + 2) % 3, cur = it % 3, nxt = (it + 1) % 3;

    if (it == 0) {
        for (int j = t; j < KK; j += 256) sv[j] = 1.0f;
    } else {
        for (int j = t; j < KK; j += 256)
            sv[j] = (float)(1.0 / (512.0 * g_sum[prev][j]));
    }
    for (int j = t; j < KK; j += 256) g_sum[nxt][j] = 0.0;
    __syncthreads();

    float4 vr[4];
    #pragma unroll
    for (int k = 0; k < 4; k++) vr[k] = *(const float4*)&sv[4 * lane + 128 * k];
    float4 cp[4];
    #pragma unroll
    for (int k = 0; k < 4; k++) cp[k] = make_float4(0.f, 0.f, 0.f, 0.f);

    for (int r = row0 + w; r < row1; r += 32) {
        int ra = r + 8, rb = r + 16, rc = r + 24;
        bool ha = ra < row1, hb = rb < row1, hc = rc < row1;
        const float4* E0 = (const float4*)&g_E[(size_t)r * KK];
        const float4* E1 = (const float4*)&g_E[(size_t)(ha ? ra : r) * KK];
        const float4* E2 = (const float4*)&g_E[(size_t)(hb ? rb : r) * KK];
        const float4* E3 = (const float4*)&g_E[(size_t)(hc ? rc : r) * KK];
        float4 e0[4], e1[4], e2[4], e3[4];
        #pragma unroll
        for (int k = 0; k < 4; k++) {
            e0[k] = E0[lane + 32 * k]; e1[k] = E1[lane + 32 * k];
            e2[k] = E2[lane + 32 * k]; e3[k] = E3[lane + 32 * k];
        }
        float d0 = 0.f, d1 = 0.f, d2 = 0.f, d3 = 0.f;
        #pragma unroll
        for (int k = 0; k < 4; k++) {
            d0 = fmaf(e0[k].x, vr[k].x, d0); d0 = fmaf(e0[k].y, vr[k].y, d0);
            d0 = fmaf(e0[k].z, vr[k].z, d0); d0 = fmaf(e0[k].w, vr[k].w, d0);
            d1 = fmaf(e1[k].x, vr[k].x, d1); d1 = fmaf(e1[k].y, vr[k].y, d1);
            d1 = fmaf(e1[k].z, vr[k].z, d1); d1 = fmaf(e1[k].w, vr[k].w, d1);
            d2 = fmaf(e2[k].x, vr[k].x, d2); d2 = fmaf(e2[k].y, vr[k].y, d2);
            d2 = fmaf(e2[k].z, vr[k].z, d2); d2 = fmaf(e2[k].w, vr[k].w, d2);
            d3 = fmaf(e3[k].x, vr[k].x, d3); d3 = fmaf(e3[k].y, vr[k].y, d3);
            d3 = fmaf(e3[k].z, vr[k].z, d3); d3 = fmaf(e3[k].w, vr[k].w, d3);
        }
        #pragma unroll
        for (int o = 16; o; o >>= 1) {
            d0 += __shfl_xor_sync(~0u, d0, o);
            d1 += __shfl_xor_sync(~0u, d1, o);
            d2 += __shfl_xor_sync(~0u, d2, o);
            d3 += __shfl_xor_sync(~0u, d3, o);
        }
        float u0 = frcp(32768.0f * d0);
        float u1 = ha ? frcp(32768.0f * d1) : 0.f;
        float u2 = hb ? frcp(32768.0f * d2) : 0.f;
        float u3 = hc ? frcp(32768.0f * d3) : 0.f;
        #pragma unroll
        for (int k = 0; k < 4; k++) {
            cp[k].x = fmaf(e0[k].x, u0, cp[k].x); cp[k].y = fmaf(e0[k].y, u0, cp[k].y);
            cp[k].z = fmaf(e0[k].z, u0, cp[k].z); cp[k].w = fmaf(e0[k].w, u0, cp[k].w);
            cp[k].x = fmaf(e1[k].x, u1, cp[k].x); cp[k].y = fmaf(e1[k].y, u1, cp[k].y);
            cp[k].z = fmaf(e1[k].z, u1, cp[k].z); cp[k].w = fmaf(e1[k].w, u1, cp[k].w);
            cp[k].x = fmaf(e2[k].x, u2, cp[k].x); cp[k].y = fmaf(e2[k].y, u2, cp[k].y);
            cp[k].z = fmaf(e2[k].z, u2, cp[k].z); cp[k].w = fmaf(e2[k].w, u2, cp[k].w);
            cp[k].x = fmaf(e3[k].x, u3, cp[k].x); cp[k].y = fmaf(e3[k].y, u3, cp[k].y);
            cp[k].z = fmaf(e3[k].z, u3, cp[k].z); cp[k].w = fmaf(e3[k].w, u3, cp[k].w);
        }
    }
    #pragma unroll
    for (int k = 0; k < 4; k++)
        *(float4*)&shS[w][4 * lane + 128 * k] = cp[k];
    __syncthreads();
    for (int j = t; j < KK; j += 256) {
        double a = 0.0;
        #pragma unroll
        for (int wi = 0; wi < 8; wi++) a += (double)shS[wi][j];
        atomicAdd(&g_sum[cur][j], a);
    }
}

__global__ void k_lnv(int last) {
    int j = threadIdx.x;  // 512
    double s = g_sum[last][j];
    if (s < 1e-300) s = 1e-300;
    g_lnv[j] = log(1.0 / (512.0 * s));
}

// final: f64 scores s_j = ln v_j - dc_ij/0.003 on frozen dc
__global__ void k_out(const float* __restrict__ x, const float* __restrict__ cb,
                      float* __restrict__ oxq, float* __restrict__ oidx) {
    int warp = (blockIdx.x * blockDim.x + threadIdx.x) >> 5;
    int lane = threadIdx.x & 31;
    if (warp >= NN) return;
    int r = warp;

    const float4* Dr = (const float4*)&g_D[(size_t)r * KK];
    double best = -1e300;
    int bidx = 0;
    #pragma unroll
    for (int k = 0; k < 4; k++) {
        float4 d = Dr[lane + 32 * k];
        int c0 = 4 * lane + 128 * k;
        float dv[4] = {d.x, d.y, d.z, d.w};
        #pragma unroll
        for (int c = 0; c < 4; c++) {
            double s = g_lnv[c0 + c] - (double)dv[c] / 0.003;
            if (s > best) { best = s; bidx = c0 + c; }
        }
    }
    #pragma unroll
    for (int o = 16; o; o >>= 1) {
        double ov = __shfl_xor_sync(~0u, best, o);
        int oi = __shfl_xor_sync(~0u, bidx, o);
        if (ov > best || (ov == best && oi < bidx)) { best = ov; bidx = oi; }
    }

    const float* c = cb + (size_t)bidx * DD;
    const float* xr = x + (size_t)r * DD;
    float a0 = c[lane], a1 = c[lane + 32];
    float x0 = xr[lane], x1 = xr[lane + 32];
    if (oxq) {
        oxq[(size_t)r * DD + lane]      = __fadd_rn(x0, __fsub_rn(a0, x0));
        oxq[(size_t)r * DD + lane + 32] = __fadd_rn(x1, __fsub_rn(a1, x1));
    }
    float d0 = __fsub_rn(a0, x0), d1 = __fsub_rn(a1, x1);
    double ls = (double)__fmul_rn(d0, d0) + (double)__fmul_rn(d1, d1);
    #pragma unroll
    for (int o = 16; o; o >>= 1) ls += __shfl_xor_sync(~0u, ls, o);
    if (lane == 0) {
        if (oidx) oidx[r] = (float)bidx;
        atomicAdd(&g_loss, ls);
    }
}

__global__ void k_loss(float* __restrict__ ol) {
    if (ol) {
        float c = (float)(g_loss / (double)((size_t)NN * DD));
        ol[0] = __fadd_rn(c, __fmul_rn(0.25f, c));
    }
}

extern "C" void kernel_launch(void* const* d_in, const int* in_sizes, int n_in,
                              void* d_out, int out_size) {
    const float* x = (const float*)d_in[0];
    const float* cb = (const float*)d_in[1];
    if (n_in >= 2 && in_sizes[0] == KK * DD && in_sizes[1] == NN * DD) {
        const float* tmp = x; x = cb; cb = tmp;
    }
    float* out = (float*)d_out;
    float* oxq = (out_size >= NN * DD) ? out : nullptr;
    float* ols = (out_size >= NN * DD + 1) ? out + (size_t)NN * DD : nullptr;
    float* oidx = (out_size >= NN * DD + 1 + NN) ? out + (size_t)NN * DD + 1 : nullptr;

    k_init<<<1, 512>>>();
    k_rx<<<NN / 8, 256>>>(x);
    k_rc<<<KK / 8, 256>>>(cb);
    k_gemm<<<NN / 128, 256>>>(x, cb);
    k_scale<<<1, 1>>>();
    k_rowE<<<NN / 8, 256>>>();
    for (int it = 0; it < SK_ITERS; it++)
        k_sink<<<NB, 256>>>(it);
    k_lnv<<<1, KK>>>((SK_ITERS - 1) % 3);
    k_out<<<NN / 8, 256>>>(x, cb, oxq, oidx);
    k_loss<<<1, 1>>>(ols);
}

// round 17
// speedup vs baseline: 1.2972x; 1.0392x over previous
#include <cuda_runtime.h>
#include <math.h>
#include <stdint.h>

#define NN 32768
#define KK 512
#define DD 64
#define SK_ITERS 100
#define NB 296
#define RPB ((NN + NB - 1) / NB)   // 111

__device__ __align__(16) float  g_E[(size_t)NN * KK];   // E (f32), 64 MiB
__device__ __align__(16) float  g_D[(size_t)NN * KK];   // d, then dc (f32)
__device__ float    g_rx[NN], g_rc[KK];
__device__ double   g_sum[3][KK];
__device__ double   g_lnv[KK];
__device__ unsigned g_dmax_u, g_dmin_u;
__device__ float    g_mid, g_amp;
__device__ double   g_inv_amp;
__device__ double   g_loss;

__global__ void k_init() {
    int t = threadIdx.x;
    if (t < KK) { g_sum[0][t] = 0.0; g_sum[1][t] = 0.0; g_sum[2][t] = 0.0; }
    if (t == 0) { g_dmax_u = 0u; g_dmin_u = 0x7f7fffffu; g_loss = 0.0; }
}

// XLA:GPU warp row-reduce (bitwise-frozen)
__global__ void k_rx(const float* __restrict__ x) {
    int warp = (blockIdx.x * blockDim.x + threadIdx.x) >> 5;
    int lane = threadIdx.x & 31;
    if (warp >= NN) return;
    const float* p = x + (size_t)warp * DD;
    float s = __fadd_rn(__fmul_rn(p[lane], p[lane]),
                        __fmul_rn(p[lane + 32], p[lane + 32]));
    #pragma unroll
    for (int o = 16; o; o >>= 1) s = __fadd_rn(s, __shfl_xor_sync(~0u, s, o));
    if (lane == 0) g_rx[warp] = s;
}
__global__ void k_rc(const float* __restrict__ cb) {
    int warp = (blockIdx.x * blockDim.x + threadIdx.x) >> 5;
    int lane = threadIdx.x & 31;
    if (warp >= KK) return;
    const float* p = cb + (size_t)warp * DD;
    float s = __fadd_rn(__fmul_rn(p[lane], p[lane]),
                        __fmul_rn(p[lane + 32], p[lane + 32]));
    #pragma unroll
    for (int o = 16; o; o >>= 1) s = __fadd_rn(s, __shfl_xor_sync(~0u, s, o));
    if (lane == 0) g_rc[warp] = s;
}

// d = fl(fl(rx+rc) - fl(2*mm)); mm = strict ascending-k single-FMA f32 chain (frozen)
__global__ __launch_bounds__(256) void k_gemm(const float* __restrict__ x,
                                              const float* __restrict__ cb) {
    __shared__ float xs[128][DD];
    __shared__ float cs[32][DD + 1];
    __shared__ float red[16];
    int b = blockIdx.x, row0 = b * 128, t = threadIdx.x;
    int jj = t & 31, rg = t >> 5;

    for (int i = t; i < 128 * DD; i += 256)
        xs[i / DD][i % DD] = x[(size_t)row0 * DD + i];

    float dmx = 0.0f, dmn = 3.4e38f;
    for (int ct = 0; ct < 16; ct++) {
        __syncthreads();
        for (int i = t; i < 32 * DD; i += 256)
            cs[i / DD][i % DD] = cb[(size_t)(ct * 32) * DD + i];
        __syncthreads();
        float cj[DD];
        #pragma unroll
        for (int k = 0; k < DD; k++) cj[k] = cs[jj][k];
        int jglob = ct * 32 + jj;
        float rcj = g_rc[jglob];

        for (int ii = 0; ii < 16; ii += 4) {
            int i0 = rg * 16 + ii;
            float a0 = 0.f, a1 = 0.f, a2 = 0.f, a3 = 0.f;
            #pragma unroll
            for (int k4 = 0; k4 < DD; k4 += 4) {
                float4 x0 = *(const float4*)&xs[i0 + 0][k4];
                float4 x1 = *(const float4*)&xs[i0 + 1][k4];
                float4 x2 = *(const float4*)&xs[i0 + 2][k4];
                float4 x3 = *(const float4*)&xs[i0 + 3][k4];
                a0 = __fmaf_rn(x0.x, cj[k4+0], a0); a0 = __fmaf_rn(x0.y, cj[k4+1], a0);
                a0 = __fmaf_rn(x0.z, cj[k4+2], a0); a0 = __fmaf_rn(x0.w, cj[k4+3], a0);
                a1 = __fmaf_rn(x1.x, cj[k4+0], a1); a1 = __fmaf_rn(x1.y, cj[k4+1], a1);
                a1 = __fmaf_rn(x1.z, cj[k4+2], a1); a1 = __fmaf_rn(x1.w, cj[k4+3], a1);
                a2 = __fmaf_rn(x2.x, cj[k4+0], a2); a2 = __fmaf_rn(x2.y, cj[k4+1], a2);
                a2 = __fmaf_rn(x2.z, cj[k4+2], a2); a2 = __fmaf_rn(x2.w, cj[k4+3], a2);
                a3 = __fmaf_rn(x3.x, cj[k4+0], a3); a3 = __fmaf_rn(x3.y, cj[k4+1], a3);
                a3 = __fmaf_rn(x3.z, cj[k4+2], a3); a3 = __fmaf_rn(x3.w, cj[k4+3], a3);
            }
            float mm[4] = {a0, a1, a2, a3};
            #pragma unroll
            for (int r = 0; r < 4; r++) {
                int i = i0 + r;
                float S = __fadd_rn(g_rx[row0 + i], rcj);
                float d = __fsub_rn(S, __fmul_rn(2.0f, mm[r]));
                dmx = fmaxf(dmx, d); dmn = fminf(dmn, d);
                g_D[(size_t)(row0 + i) * KK + jglob] = d;
            }
        }
    }
    #pragma unroll
    for (int o = 16; o; o >>= 1) {
        dmx = fmaxf(dmx, __shfl_xor_sync(~0u, dmx, o));
        dmn = fminf(dmn, __shfl_xor_sync(~0u, dmn, o));
    }
    int w = t >> 5;
    if ((t & 31) == 0) { red[w] = dmx; red[w + 8] = dmn; }
    __syncthreads();
    if (t == 0) {
        float m = red[0], n = red[8];
        for (int i = 1; i < 8; i++) { m = fmaxf(m, red[i]); n = fminf(n, red[i + 8]); }
        atomicMax(&g_dmax_u, __float_as_uint(m));
        atomicMin(&g_dmin_u, __float_as_uint(n));
    }
}

__global__ void k_scale() {
    float dmax = __uint_as_float(g_dmax_u), dmin = __uint_as_float(g_dmin_u);
    float mid = __fmul_rn(__fadd_rn(dmax, dmin), 0.5f);
    float amp = __fadd_rn(__fsub_rn(dmax, mid), 1e-5f);
    g_mid = mid;
    g_amp = amp;
    g_inv_amp = 1.0 / (double)amp;
}

// dc = fl32((d-mid)*fl64(1/amp))  [== fl32((d-mid)/amp) except ~2^-52-boundary cases]
// E = expf((rmin-dc)/eps) -> g_E
__global__ __launch_bounds__(256) void k_rowE() {
    int warp = (blockIdx.x * blockDim.x + threadIdx.x) >> 5;
    int lane = threadIdx.x & 31;
    if (warp >= NN) return;
    float mid = g_mid;
    double ia = g_inv_amp;
    float4* Dr = (float4*)&g_D[(size_t)warp * KK];
    float4* Er = (float4*)&g_E[(size_t)warp * KK];

    float4 dcv[4];
    float rmin = 3.4e38f;
    #pragma unroll
    for (int k = 0; k < 4; k++) {
        float4 d = Dr[lane + 32 * k];
        d.x = (float)((double)__fsub_rn(d.x, mid) * ia);
        d.y = (float)((double)__fsub_rn(d.y, mid) * ia);
        d.z = (float)((double)__fsub_rn(d.z, mid) * ia);
        d.w = (float)((double)__fsub_rn(d.w, mid) * ia);
        rmin = fminf(rmin, fminf(fminf(d.x, d.y), fminf(d.z, d.w)));
        dcv[k] = d;
    }
    #pragma unroll
    for (int o = 16; o; o >>= 1) rmin = fminf(rmin, __shfl_xor_sync(~0u, rmin, o));

    const float INV_EPS = 333.33333333333333f;
    #pragma unroll
    for (int k = 0; k < 4; k++) {
        float4 d = dcv[k], e;
        Dr[lane + 32 * k] = d;
        e.x = expf(__fmul_rn(__fsub_rn(rmin, d.x), INV_EPS));
        e.y = expf(__fmul_rn(__fsub_rn(rmin, d.y), INV_EPS));
        e.z = expf(__fmul_rn(__fsub_rn(rmin, d.z), INV_EPS));
        e.w = expf(__fmul_rn(__fsub_rn(rmin, d.w), INV_EPS));
        Er[lane + 32 * k] = e;
    }
}

__device__ __forceinline__ float frcp(float a) {
    float r;
    asm("rcp.approx.f32 %0, %1;" : "=f"(r) : "f"(a));
    return r;
}

// one Sinkhorn iteration: 4-row ILP, rcp.approx u, FP64-free head.
__global__ __launch_bounds__(256, 2) void k_sink(int it) {
    __shared__ float sv[KK];
    __shared__ float shS[8][KK];   // 16 KB
    int b = blockIdx.x, t = threadIdx.x, w = t >> 5, lane = t & 31;
    int row0 = b * RPB, row1 = min(row0 + RPB, NN);
    int prev = (it + 2) % 3, cur = it % 3, nxt = (it + 1) % 3;

    if (it == 0) {
        for (int j = t; j < KK; j += 256) sv[j] = 1.0f;
    } else {
        for (int j = t; j < KK; j += 256)
            sv[j] = frcp(512.0f * (float)g_sum[prev][j]);
    }
    for (int j = t; j < KK; j += 256) g_sum[nxt][j] = 0.0;
    __syncthreads();

    float4 vr[4];
    #pragma unroll
    for (int k = 0; k < 4; k++) vr[k] = *(const float4*)&sv[4 * lane + 128 * k];
    float4 cp[4];
    #pragma unroll
    for (int k = 0; k < 4; k++) cp[k] = make_float4(0.f, 0.f, 0.f, 0.f);

    for (int r = row0 + w; r < row1; r += 32) {
        int ra = r + 8, rb = r + 16, rc = r + 24;
        bool ha = ra < row1, hb = rb < row1, hc = rc < row1;
        const float4* E0 = (const float4*)&g_E[(size_t)r * KK];
        const float4* E1 = (const float4*)&g_E[(size_t)(ha ? ra : r) * KK];
        const float4* E2 = (const float4*)&g_E[(size_t)(hb ? rb : r) * KK];
        const float4* E3 = (const float4*)&g_E[(size_t)(hc ? rc : r) * KK];
        float4 e0[4], e1[4], e2[4], e3[4];
        #pragma unroll
        for (int k = 0; k < 4; k++) {
            e0[k] = E0[lane + 32 * k]; e1[k] = E1[lane + 32 * k];
            e2[k] = E2[lane + 32 * k]; e3[k] = E3[lane + 32 * k];
        }
        float d0 = 0.f, d1 = 0.f, d2 = 0.f, d3 = 0.f;
        #pragma unroll
        for (int k = 0; k < 4; k++) {
            d0 = fmaf(e0[k].x, vr[k].x, d0); d0 = fmaf(e0[k].y, vr[k].y, d0);
            d0 = fmaf(e0[k].z, vr[k].z, d0); d0 = fmaf(e0[k].w, vr[k].w, d0);
            d1 = fmaf(e1[k].x, vr[k].x, d1); d1 = fmaf(e1[k].y, vr[k].y, d1);
            d1 = fmaf(e1[k].z, vr[k].z, d1); d1 = fmaf(e1[k].w, vr[k].w, d1);
            d2 = fmaf(e2[k].x, vr[k].x, d2); d2 = fmaf(e2[k].y, vr[k].y, d2);
            d2 = fmaf(e2[k].z, vr[k].z, d2); d2 = fmaf(e2[k].w, vr[k].w, d2);
            d3 = fmaf(e3[k].x, vr[k].x, d3); d3 = fmaf(e3[k].y, vr[k].y, d3);
            d3 = fmaf(e3[k].z, vr[k].z, d3); d3 = fmaf(e3[k].w, vr[k].w, d3);
        }
        #pragma unroll
        for (int o = 16; o; o >>= 1) {
            d0 += __shfl_xor_sync(~0u, d0, o);
            d1 += __shfl_xor_sync(~0u, d1, o);
            d2 += __shfl_xor_sync(~0u, d2, o);
            d3 += __shfl_xor_sync(~0u, d3, o);
        }
        float u0 = frcp(32768.0f * d0);
        float u1 = ha ? frcp(32768.0f * d1) : 0.f;
        float u2 = hb ? frcp(32768.0f * d2) : 0.f;
        float u3 = hc ? frcp(32768.0f * d3) : 0.f;
        #pragma unroll
        for (int k = 0; k < 4; k++) {
            cp[k].x = fmaf(e0[k].x, u0, cp[k].x); cp[k].y = fmaf(e0[k].y, u0, cp[k].y);
            cp[k].z = fmaf(e0[k].z, u0, cp[k].z); cp[k].w = fmaf(e0[k].w, u0, cp[k].w);
            cp[k].x = fmaf(e1[k].x, u1, cp[k].x); cp[k].y = fmaf(e1[k].y, u1, cp[k].y);
            cp[k].z = fmaf(e1[k].z, u1, cp[k].z); cp[k].w = fmaf(e1[k].w, u1, cp[k].w);
            cp[k].x = fmaf(e2[k].x, u2, cp[k].x); cp[k].y = fmaf(e2[k].y, u2, cp[k].y);
            cp[k].z = fmaf(e2[k].z, u2, cp[k].z); cp[k].w = fmaf(e2[k].w, u2, cp[k].w);
            cp[k].x = fmaf(e3[k].x, u3, cp[k].x); cp[k].y = fmaf(e3[k].y, u3, cp[k].y);
            cp[k].z = fmaf(e3[k].z, u3, cp[k].z); cp[k].w = fmaf(e3[k].w, u3, cp[k].w);
        }
    }
    #pragma unroll
    for (int k = 0; k < 4; k++)
        *(float4*)&shS[w][4 * lane + 128 * k] = cp[k];
    __syncthreads();
    for (int j = t; j < KK; j += 256) {
        double a = 0.0;
        #pragma unroll
        for (int wi = 0; wi < 8; wi++) a += (double)shS[wi][j];
        atomicAdd(&g_sum[cur][j], a);
    }
}

__global__ void k_lnv(int last) {
    int j = threadIdx.x;  // 512
    double s = g_sum[last][j];
    if (s < 1e-300) s = 1e-300;
    g_lnv[j] = log(1.0 / (512.0 * s));
}

// final: f64 scores s_j = ln v_j - dc_ij/0.003 on frozen dc
__global__ void k_out(const float* __restrict__ x, const float* __restrict__ cb,
                      float* __restrict__ oxq, float* __restrict__ oidx) {
    int warp = (blockIdx.x * blockDim.x + threadIdx.x) >> 5;
    int lane = threadIdx.x & 31;
    if (warp >= NN) return;
    int r = warp;

    const float4* Dr = (const float4*)&g_D[(size_t)r * KK];
    double best = -1e300;
    int bidx = 0;
    #pragma unroll
    for (int k = 0; k < 4; k++) {
        float4 d = Dr[lane + 32 * k];
        int c0 = 4 * lane + 128 * k;
        float dv[4] = {d.x, d.y, d.z, d.w};
        #pragma unroll
        for (int c = 0; c < 4; c++) {
            double s = g_lnv[c0 + c] - (double)dv[c] / 0.003;
            if (s > best) { best = s; bidx = c0 + c; }
        }
    }
    #pragma unroll
    for (int o = 16; o; o >>= 1) {
        double ov = __shfl_xor_sync(~0u, best, o);
        int oi = __shfl_xor_sync(~0u, bidx, o);
        if (ov > best || (ov == best && oi < bidx)) { best = ov; bidx = oi; }
    }

    const float* c = cb + (size_t)bidx * DD;
    const float* xr = x + (size_t)r * DD;
    float a0 = c[lane], a1 = c[lane + 32];
    float x0 = xr[lane], x1 = xr[lane + 32];
    if (oxq) {
        oxq[(size_t)r * DD + lane]      = __fadd_rn(x0, __fsub_rn(a0, x0));
        oxq[(size_t)r * DD + lane + 32] = __fadd_rn(x1, __fsub_rn(a1, x1));
    }
    float d0 = __fsub_rn(a0, x0), d1 = __fsub_rn(a1, x1);
    double ls = (double)__fmul_rn(d0, d0) + (double)__fmul_rn(d1, d1);
    #pragma unroll
    for (int o = 16; o; o >>= 1) ls += __shfl_xor_sync(~0u, ls, o);
    if (lane == 0) {
        if (oidx) oidx[r] = (float)bidx;
        atomicAdd(&g_loss, ls);
    }
}

__global__ void k_loss(float* __restrict__ ol) {
    if (ol) {
        float c = (float)(g_loss / (double)((size_t)NN * DD));
        ol[0] = __fadd_rn(c, __fmul_rn(0.25f, c));
    }
}

extern "C" void kernel_launch(void* const* d_in, const int* in_sizes, int n_in,
                              void* d_out, int out_size) {
    const float* x = (const float*)d_in[0];
    const float* cb = (const float*)d_in[1];
    if (n_in >= 2 && in_sizes[0] == KK * DD && in_sizes[1] == NN * DD) {
        const float* tmp = x; x = cb; cb = tmp;
    }
    float* out = (float*)d_out;
    float* oxq = (out_size >= NN * DD) ? out : nullptr;
    float* ols = (out_size >= NN * DD + 1) ? out + (size_t)NN * DD : nullptr;
    float* oidx = (out_size >= NN * DD + 1 + NN) ? out + (size_t)NN * DD + 1 : nullptr;

    k_init<<<1, 512>>>();
    k_rx<<<NN / 8, 256>>>(x);
    k_rc<<<KK / 8, 256>>>(cb);
    k_gemm<<<NN / 128, 256>>>(x, cb);
    k_scale<<<1, 1>>>();
    k_rowE<<<NN / 8, 256>>>();
    for (int it = 0; it < SK_ITERS; it++)
        k_sink<<<NB, 256>>>(it);
    k_lnv<<<1, KK>>>((SK_ITERS - 1) % 3);
    k_out<<<NN / 8, 256>>>(x, cb, oxq, oidx);
    k_loss<<<1, 1>>>(ols);
}